// round 5
// baseline (speedup 1.0000x reference)
#include <cuda_runtime.h>
#include <math.h>

#define FEAT 128
#define HID  64
#define NMAX 50048
#define EMAX 1048576

// ---------------- scratch (static __device__) ----------------
__device__ float g_h[NMAX * FEAT];      // post-GEMM features h
__device__ float g_y[NMAX * HID];       // post-aggregation features (relu'd, pre-BN)
__device__ float g_as[NMAX];            // alpha_src per node
__device__ float g_ad[NMAX];            // alpha_dst per node
__device__ int2  g_sd[EMAX];            // packed (src, dst) in original order
__device__ int   g_csrc[EMAX];          // CSR: src sorted by dst
__device__ int   g_cnt[NMAX];           // in-degree histogram
__device__ int   g_rowptr[NMAX + 1];    // CSR row pointers
__device__ int   g_cursor[NMAX];        // scatter cursors
__device__ float g_colsum[4 * FEAT];    // per-layer BN stat slots
__device__ float g_colsq[4 * FEAT];
__device__ int   g_is64;

// ---------------- startup: zero histogram + stat slots, detect index dtype ----------------
__global__ void start_kernel(const void* ei, int n) {
    int i = blockIdx.x * blockDim.x + threadIdx.x;
    if (i < n) g_cnt[i] = 0;
    if (i < 4 * FEAT) { g_colsum[i] = 0.f; g_colsq[i] = 0.f; }
    if (blockIdx.x == 0 && threadIdx.x < 32) {
        const long long* p = (const long long*)ei;
        int bad = 0;
        for (int k = threadIdx.x; k < 64; k += 32) {
            long long v = p[k];
            if (v < 0 || v >= (1LL << 31)) bad = 1;
        }
        bad = __any_sync(0xffffffffu, bad);
        if (threadIdx.x == 0) g_is64 = bad ? 0 : 1;
    }
}

// ---------------- convert + degree histogram ----------------
__global__ void convert_kernel(const void* ei, int E, int ET) {
    int i = blockIdx.x * blockDim.x + threadIdx.x;
    if (i >= ET) return;
    int s, d;
    if (i < E) {
        if (g_is64) {
            const long long* p = (const long long*)ei;
            s = (int)p[i]; d = (int)p[E + i];
        } else {
            const int* p = (const int*)ei;
            s = p[i]; d = p[E + i];
        }
    } else {
        s = i - E; d = i - E;
    }
    g_sd[i] = make_int2(s, d);
    atomicAdd(&g_cnt[d], 1);
}

// ---------------- exclusive scan of degrees -> rowptr + cursors (1 block) ----------------
__global__ void scan_kernel(int n) {
    __shared__ int sp[1024];
    int tid = threadIdx.x;
    int chunk = (n + 1023) / 1024;
    int b = tid * chunk;
    int e = min(b + chunk, n);
    int s = 0;
    for (int i = b; i < e; i++) s += g_cnt[i];
    sp[tid] = s;
    __syncthreads();
    // Hillis-Steele inclusive scan
    for (int off = 1; off < 1024; off <<= 1) {
        int v = (tid >= off) ? sp[tid - off] : 0;
        __syncthreads();
        sp[tid] += v;
        __syncthreads();
    }
    int pre = (tid > 0) ? sp[tid - 1] : 0;
    for (int i = b; i < e; i++) {
        g_rowptr[i] = pre;
        g_cursor[i] = pre;
        pre += g_cnt[i];
    }
    if (tid == 0) g_rowptr[n] = sp[1023];
}

// ---------------- scatter edges into CSR ----------------
__global__ void scatter_kernel(int ET) {
    int i = blockIdx.x * blockDim.x + threadIdx.x;
    if (i >= ET) return;
    int2 sd = g_sd[i];
    int pos = atomicAdd(&g_cursor[sd.y], 1);
    g_csrc[pos] = sd.x;
}

// ---------------- GEMM: h = affine(x) @ W^T, fused BN-finalize + alpha epilogue ----------
// Block 256 threads; tile M x OUT, M = 8192/OUT; thread tile 4 x 8.
template <int IN, int OUT>
__global__ void gemm_kernel(const float* __restrict__ x, const float* __restrict__ W,
                            const float* __restrict__ gamma, const float* __restrict__ beta,
                            const float* __restrict__ colsum, const float* __restrict__ colsq,
                            float invn, int useAffine,
                            const float* __restrict__ avs, const float* __restrict__ avd,
                            float* __restrict__ h, int n) {
    const int M = 8192 / OUT;          // 128 (OUT=64) or 64 (OUT=128)
    const int OC = OUT / 8;            // col groups: 8 or 16
    const int KC = 32;
    const int SXS = M + 4;
    const int SWS = OUT + 4;

    __shared__ __align__(16) float sSc[IN];
    __shared__ __align__(16) float sSh[IN];
    __shared__ __align__(16) float sX[KC * SXS];
    __shared__ __align__(16) float sW[KC * SWS];

    int tid = threadIdx.x;
    int og = tid % OC;
    int rg = tid / OC;
    int r0 = blockIdx.x * M;

    if (useAffine) {
        for (int o = tid; o < IN; o += 256) {
            float mu = colsum[o] * invn;
            float var = colsq[o] * invn - mu * mu;
            float sc = gamma[o] * rsqrtf(var + 1e-5f);
            sSc[o] = sc;
            sSh[o] = beta[o] - mu * sc;
        }
        __syncthreads();
    }

    float acc[4][8];
#pragma unroll
    for (int i = 0; i < 4; i++)
#pragma unroll
        for (int j = 0; j < 8; j++) acc[i][j] = 0.f;

    for (int kc = 0; kc < IN; kc += KC) {
        for (int idx = tid; idx < M * (KC / 4); idx += 256) {
            int r = idx >> 3, q = idx & 7;
            int k = q * 4;
            int row = r0 + r;
            float4 v = (row < n) ? *(const float4*)&x[row * IN + kc + k]
                                 : make_float4(0.f, 0.f, 0.f, 0.f);
            if (useAffine) {
                v.x = v.x * sSc[kc + k] + sSh[kc + k];
                v.y = v.y * sSc[kc + k + 1] + sSh[kc + k + 1];
                v.z = v.z * sSc[kc + k + 2] + sSh[kc + k + 2];
                v.w = v.w * sSc[kc + k + 3] + sSh[kc + k + 3];
            }
            sX[(k + 0) * SXS + r] = v.x;
            sX[(k + 1) * SXS + r] = v.y;
            sX[(k + 2) * SXS + r] = v.z;
            sX[(k + 3) * SXS + r] = v.w;
        }
        for (int idx = tid; idx < OUT * (KC / 4); idx += 256) {
            int o = idx >> 3, q = idx & 7;
            int k = q * 4;
            float4 w = *(const float4*)&W[o * IN + kc + k];
            sW[(k + 0) * SWS + o] = w.x;
            sW[(k + 1) * SWS + o] = w.y;
            sW[(k + 2) * SWS + o] = w.z;
            sW[(k + 3) * SWS + o] = w.w;
        }
        __syncthreads();

#pragma unroll
        for (int k = 0; k < KC; k++) {
            float4 a  = *(const float4*)&sX[k * SXS + rg * 4];
            float4 b0 = *(const float4*)&sW[k * SWS + og * 8];
            float4 b1 = *(const float4*)&sW[k * SWS + og * 8 + 4];
            float av[4] = {a.x, a.y, a.z, a.w};
            float bv[8] = {b0.x, b0.y, b0.z, b0.w, b1.x, b1.y, b1.z, b1.w};
#pragma unroll
            for (int i = 0; i < 4; i++)
#pragma unroll
                for (int j = 0; j < 8; j++)
                    acc[i][j] += av[i] * bv[j];
        }
        __syncthreads();
    }

    float avsr[8], avdr[8];
#pragma unroll
    for (int j = 0; j < 8; j++) {
        avsr[j] = __ldg(&avs[og * 8 + j]);
        avdr[j] = __ldg(&avd[og * 8 + j]);
    }

    float* sP = sX;
    float* sQ = sX + M * OC;
#pragma unroll
    for (int i = 0; i < 4; i++) {
        int rl = rg * 4 + i;
        int row = r0 + rl;
        float ps = 0.f, pd = 0.f;
#pragma unroll
        for (int j = 0; j < 8; j++) {
            ps += acc[i][j] * avsr[j];
            pd += acc[i][j] * avdr[j];
        }
        sP[rl * OC + og] = ps;
        sQ[rl * OC + og] = pd;
        if (row < n) {
            float4 v0 = make_float4(acc[i][0], acc[i][1], acc[i][2], acc[i][3]);
            float4 v1 = make_float4(acc[i][4], acc[i][5], acc[i][6], acc[i][7]);
            *(float4*)&h[row * OUT + og * 8] = v0;
            *(float4*)&h[row * OUT + og * 8 + 4] = v1;
        }
    }
    __syncthreads();
    if (tid < M) {
        int row = r0 + tid;
        if (row < n) {
            float as = 0.f, ad = 0.f;
#pragma unroll
            for (int t = 0; t < OC; t++) {
                as += sP[tid * OC + t];
                ad += sQ[tid * OC + t];
            }
            g_as[row] = as;
            g_ad[row] = ad;
        }
    }
}

// ---------------- fused CSR aggregation ----------------
// Warp per node (grid-stride): softmax over in-edges (local, no atomics),
// register-accumulated gather of alpha*h[src], then fused epilogue:
//   MODE 0: y = relu(acc + b), accumulate BN column stats (flushed once per warp)
//   MODE 1: x_hat = relu(acc + b); out = [|x - x_hat|, x_hat]
template <int OUT, int MODE>
__global__ void edge_agg_kernel(const float* __restrict__ h, const float* __restrict__ b,
                                const float* __restrict__ x, float* __restrict__ yout,
                                float* __restrict__ colsum, float* __restrict__ colsq,
                                int n, int out_size) {
    const int CPL = OUT / 32;               // columns per lane: 2 or 4
    int lane = threadIdx.x & 31;
    int warp = (blockIdx.x * blockDim.x + threadIdx.x) >> 5;
    int nwarps = (gridDim.x * blockDim.x) >> 5;

    float bias[CPL];
#pragma unroll
    for (int c = 0; c < CPL; c++) bias[c] = __ldg(&b[lane * CPL + c]);

    float stat_s[CPL], stat_q[CPL];
#pragma unroll
    for (int c = 0; c < CPL; c++) { stat_s[c] = 0.f; stat_q[c] = 0.f; }

    for (int node = warp; node < n; node += nwarps) {
        int start = g_rowptr[node];
        int deg = g_rowptr[node + 1] - start;
        float adn = g_ad[node];

        // ---- phase A: per-lane e values (4 cached chunks = deg<=128), softmax sum ----
        float e_reg[4];
        int   s_reg[4];
        float lsum = 0.f;
#pragma unroll
        for (int c = 0; c < 4; c++) {
            e_reg[c] = 0.f; s_reg[c] = 0;
            int j = c * 32 + lane;
            if (j < deg) {
                int s = g_csrc[start + j];
                float e = g_as[s] + adn;
                e = (e >= 0.f) ? e : 0.2f * e;
                e = __expf(e);
                e_reg[c] = e; s_reg[c] = s;
                lsum += e;
            }
        }
        for (int base = 128; base < deg; base += 32) {   // overflow (rare/never)
            int j = base + lane;
            if (j < deg) {
                int s = g_csrc[start + j];
                float e = g_as[s] + adn;
                e = (e >= 0.f) ? e : 0.2f * e;
                lsum += __expf(e);
            }
        }
#pragma unroll
        for (int off = 16; off; off >>= 1)
            lsum += __shfl_xor_sync(0xffffffffu, lsum, off);
        float inv = __fdividef(1.f, lsum + 1e-16f);

        // ---- phase B: gather alpha * h[src] into registers ----
        float acc[CPL];
#pragma unroll
        for (int c = 0; c < CPL; c++) acc[c] = 0.f;

#pragma unroll
        for (int c = 0; c < 4; c++) {
            int base = c * 32;
            if (base >= deg) break;                       // uniform across warp
            int cnt = min(32, deg - base);
            float al = e_reg[c] * inv;
            for (int t = 0; t < cnt; t++) {
                float a = __shfl_sync(0xffffffffu, al, t);
                int   s = __shfl_sync(0xffffffffu, s_reg[c], t);
                if (CPL == 2) {
                    float2 hv = *(const float2*)&h[s * OUT + lane * 2];
                    acc[0] += a * hv.x;
                    acc[1] += a * hv.y;
                } else {
                    float4 hv = *(const float4*)&h[s * OUT + lane * 4];
                    acc[0] += a * hv.x;
                    acc[1] += a * hv.y;
                    acc[2] += a * hv.z;
                    acc[3] += a * hv.w;
                }
            }
        }
        for (int base = 128; base < deg; base += 32) {    // overflow: recompute e
            int j = base + lane;
            float e = 0.f; int sl = 0;
            if (j < deg) {
                sl = g_csrc[start + j];
                float ev = g_as[sl] + adn;
                ev = (ev >= 0.f) ? ev : 0.2f * ev;
                e = __expf(ev);
            }
            float al = e * inv;
            int cnt = min(32, deg - base);
            for (int t = 0; t < cnt; t++) {
                float a = __shfl_sync(0xffffffffu, al, t);
                int   s = __shfl_sync(0xffffffffu, sl, t);
                if (CPL == 2) {
                    float2 hv = *(const float2*)&h[s * OUT + lane * 2];
                    acc[0] += a * hv.x;
                    acc[1] += a * hv.y;
                } else {
                    float4 hv = *(const float4*)&h[s * OUT + lane * 4];
                    acc[0] += a * hv.x;
                    acc[1] += a * hv.y;
                    acc[2] += a * hv.z;
                    acc[3] += a * hv.w;
                }
            }
        }

        // ---- epilogue ----
        if (MODE == 0) {
            float2 v;
            v.x = acc[0] + bias[0]; v.x = (v.x > 0.f) ? v.x : 0.f;
            v.y = acc[1] + bias[1]; v.y = (v.y > 0.f) ? v.y : 0.f;
            *(float2*)&yout[node * OUT + lane * 2] = v;
            stat_s[0] += v.x; stat_q[0] += v.x * v.x;
            stat_s[1] += v.y; stat_q[1] += v.y * v.y;
        } else {
            float v[4];
#pragma unroll
            for (int c = 0; c < 4; c++) {
                v[c] = acc[c] + bias[c];
                v[c] = (v[c] > 0.f) ? v[c] : 0.f;
            }
            float4 xv = *(const float4*)&x[node * OUT + lane * 4];
            float4 dv = make_float4(fabsf(xv.x - v[0]), fabsf(xv.y - v[1]),
                                    fabsf(xv.z - v[2]), fabsf(xv.w - v[3]));
            *(float4*)&yout[node * OUT + lane * 4] = dv;
            int total = n * OUT;
            if (out_size >= 2 * total)
                *(float4*)&yout[total + node * OUT + lane * 4] =
                    make_float4(v[0], v[1], v[2], v[3]);
        }
    }

    if (MODE == 0) {
#pragma unroll
        for (int c = 0; c < CPL; c++) {
            atomicAdd(&colsum[lane * CPL + c], stat_s[c]);
            atomicAdd(&colsq[lane * CPL + c], stat_q[c]);
        }
    }
}

extern "C" void kernel_launch(void* const* d_in, const int* in_sizes, int n_in,
                              void* d_out, int out_size) {
    const float* x   = (const float*)d_in[0];
    const void*  ei  = d_in[1];
    const float* W1  = (const float*)d_in[2];
    const float* a1s = (const float*)d_in[3];
    const float* a1d = (const float*)d_in[4];
    const float* b1  = (const float*)d_in[5];
    const float* g1  = (const float*)d_in[6];
    const float* be1 = (const float*)d_in[7];
    const float* W2  = (const float*)d_in[8];
    const float* a2s = (const float*)d_in[9];
    const float* a2d = (const float*)d_in[10];
    const float* b2  = (const float*)d_in[11];
    const float* g2  = (const float*)d_in[12];
    const float* be2 = (const float*)d_in[13];
    const float* W3  = (const float*)d_in[14];
    const float* a3s = (const float*)d_in[15];
    const float* a3d = (const float*)d_in[16];
    const float* b3  = (const float*)d_in[17];
    const float* g3  = (const float*)d_in[18];
    const float* be3 = (const float*)d_in[19];
    const float* W4  = (const float*)d_in[20];
    const float* a4s = (const float*)d_in[21];
    const float* a4d = (const float*)d_in[22];
    const float* b4  = (const float*)d_in[23];

    int n  = in_sizes[0] / FEAT;     // 50000
    int E  = in_sizes[1] / 2;        // 800000
    int ET = E + n;

    float *hbuf, *ybuf, *csum, *csq;
    cudaGetSymbolAddress((void**)&hbuf, g_h);
    cudaGetSymbolAddress((void**)&ybuf, g_y);
    cudaGetSymbolAddress((void**)&csum, g_colsum);
    cudaGetSymbolAddress((void**)&csq,  g_colsq);

    float invn = 1.0f / (float)n;
    const int AGG_BLOCKS = 592;                 // grid-stride warps for BN layers

    // ---- CSR build ----
    start_kernel<<<(n + 255) / 256, 256>>>(ei, n);
    convert_kernel<<<(ET + 255) / 256, 256>>>(ei, E, ET);
    scan_kernel<<<1, 1024>>>(n);
    scatter_kernel<<<(ET + 255) / 256, 256>>>(ET);

    // ---- Layer 1: 128 -> 64 ----
    gemm_kernel<FEAT, HID><<<(n + 127) / 128, 256>>>(
        x, W1, nullptr, nullptr, nullptr, nullptr, invn, 0, a1s, a1d, hbuf, n);
    edge_agg_kernel<HID, 0><<<AGG_BLOCKS, 256>>>(
        hbuf, b1, nullptr, ybuf, csum + 0 * FEAT, csq + 0 * FEAT, n, 0);

    // ---- Layer 2: 64 -> 64 (BN1 folded into GEMM) ----
    gemm_kernel<HID, HID><<<(n + 127) / 128, 256>>>(
        ybuf, W2, g1, be1, csum + 0 * FEAT, csq + 0 * FEAT, invn, 1, a2s, a2d, hbuf, n);
    edge_agg_kernel<HID, 0><<<AGG_BLOCKS, 256>>>(
        hbuf, b2, nullptr, ybuf, csum + 1 * FEAT, csq + 1 * FEAT, n, 0);

    // ---- Layer 3: 64 -> 64 ----
    gemm_kernel<HID, HID><<<(n + 127) / 128, 256>>>(
        ybuf, W3, g2, be2, csum + 1 * FEAT, csq + 1 * FEAT, invn, 1, a3s, a3d, hbuf, n);
    edge_agg_kernel<HID, 0><<<AGG_BLOCKS, 256>>>(
        hbuf, b3, nullptr, ybuf, csum + 2 * FEAT, csq + 2 * FEAT, n, 0);

    // ---- Layer 4: 64 -> 128, fused final output ----
    gemm_kernel<HID, FEAT><<<(n + 63) / 64, 256>>>(
        ybuf, W4, g3, be3, csum + 2 * FEAT, csq + 2 * FEAT, invn, 1, a4s, a4d, hbuf, n);
    edge_agg_kernel<FEAT, 1><<<(n * 32 + 255) / 256, 256>>>(
        hbuf, b4, x, (float*)d_out, nullptr, nullptr, n, out_size);
}